// round 3
// baseline (speedup 1.0000x reference)
#include <cuda_runtime.h>
#include <cuda_fp16.h>
#include <cstdint>

// ---------------------------------------------------------------------------
// BitLinear 1.58b on sm_103 (baseline PTX only):
//   y[m,o] = s_w[o] * sum_k z[m,k] * t[o,k]
//   z = absmax fake-quant of x (fp16), t = ternary weights {-1,0,1} (fp16)
// quant_x / quant_w -> PERSISTENT pipelined cp.async + ldmatrix + mma.sync GEMM
// with cross-tile prefetch (epilogue overlaps next tile's pipeline fill).
// ---------------------------------------------------------------------------

static constexpr int M_TOT = 8192;
static constexpr int K_TOT = 4096;
static constexpr int N_TOT = 4096;

static constexpr int TILE_M = 128;
static constexpr int TILE_N = 256;
static constexpr int TILE_K = 32;
static constexpr int NK     = K_TOT / TILE_K;   // 128
static constexpr int STAGES = 4;
static constexpr int NUM_NT = N_TOT / TILE_N;   // 16
static constexpr int NUM_MT = M_TOT / TILE_M;   // 64
static constexpr int NTILES = NUM_NT * NUM_MT;  // 1024

static constexpr int A_STAGE = TILE_M * TILE_K * 2;      // 8192 B
static constexpr int B_STAGE = TILE_N * TILE_K * 2;      // 16384 B
static constexpr int STAGE_BYTES = A_STAGE + B_STAGE;    // 24576 B
static constexpr int SMEM_DYN = STAGES * STAGE_BYTES;    // 98304 B

__device__ __align__(16) __half g_z [(size_t)M_TOT * K_TOT];   // 64 MB
__device__ __align__(16) __half g_wt[(size_t)N_TOT * K_TOT];   // 32 MB
__device__ float g_sw[N_TOT];

// ---------------------------------------------------------------------------
__device__ __forceinline__ uint32_t smem_u32(const void* p) {
    uint32_t a;
    asm("{ .reg .u64 t; cvta.to.shared.u64 t, %1; cvt.u32.u64 %0, t; }" : "=r"(a) : "l"(p));
    return a;
}
__device__ __forceinline__ void cp_async16(uint32_t saddr, const void* g) {
    asm volatile("cp.async.cg.shared.global [%0], [%1], 16;" :: "r"(saddr), "l"(g) : "memory");
}
__device__ __forceinline__ void cp_commit() {
    asm volatile("cp.async.commit_group;" ::: "memory");
}
template<int N> __device__ __forceinline__ void cp_wait() {
    asm volatile("cp.async.wait_group %0;" :: "n"(N) : "memory");
}
__device__ __forceinline__ void ldsm4(uint32_t* r, uint32_t addr) {
    asm volatile("ldmatrix.sync.aligned.m8n8.x4.shared.b16 {%0,%1,%2,%3}, [%4];"
                 : "=r"(r[0]), "=r"(r[1]), "=r"(r[2]), "=r"(r[3]) : "r"(addr));
}
__device__ __forceinline__ void mma16816(float* c, const uint32_t* a, uint32_t b0, uint32_t b1) {
    asm volatile(
        "mma.sync.aligned.m16n8k16.row.col.f32.f16.f16.f32 "
        "{%0,%1,%2,%3}, {%4,%5,%6,%7}, {%8,%9}, {%0,%1,%2,%3};"
        : "+f"(c[0]), "+f"(c[1]), "+f"(c[2]), "+f"(c[3])
        : "r"(a[0]), "r"(a[1]), "r"(a[2]), "r"(a[3]), "r"(b0), "r"(b1));
}

// ---------------------------------------------------------------------------
// quantize x: per-token groups of 64, absmax fake-quant -> fp16 row-major
// ---------------------------------------------------------------------------
__global__ void __launch_bounds__(256) quant_x_kernel(const float* __restrict__ x) {
    const int m = blockIdx.x;
    const int t = threadIdx.x;

    const float4* xp = reinterpret_cast<const float4*>(x + (size_t)m * K_TOT + t * 16);
    float v[16];
#pragma unroll
    for (int i = 0; i < 4; ++i) {
        float4 f = xp[i];
        v[4*i+0] = f.x; v[4*i+1] = f.y; v[4*i+2] = f.z; v[4*i+3] = f.w;
    }

    float am = 0.f;
#pragma unroll
    for (int i = 0; i < 16; ++i) am = fmaxf(am, fabsf(v[i]));
    am = fmaxf(am, __shfl_xor_sync(0xffffffffu, am, 1));
    am = fmaxf(am, __shfl_xor_sync(0xffffffffu, am, 2));
    am = fmaxf(am, 1e-5f);
    const float scale = 127.0f / am;
    const float inv   = am * (1.0f / 127.0f);

    uint32_t p[8];
#pragma unroll
    for (int i = 0; i < 8; ++i) {
        float q0 = fminf(fmaxf(rintf(v[2*i+0] * scale), -127.f), 127.f) * inv;
        float q1 = fminf(fmaxf(rintf(v[2*i+1] * scale), -127.f), 127.f) * inv;
        __half2 h = __floats2half2_rn(q0, q1);
        p[i] = *reinterpret_cast<uint32_t*>(&h);
    }

    uint4* dst = reinterpret_cast<uint4*>(g_z + (size_t)m * K_TOT + t * 16);
    dst[0] = make_uint4(p[0], p[1], p[2], p[3]);
    dst[1] = make_uint4(p[4], p[5], p[6], p[7]);
}

// ---------------------------------------------------------------------------
// quantize w: per-row absmean ternary -> fp16 {-1,0,1}; s_w fp32
// ---------------------------------------------------------------------------
__global__ void __launch_bounds__(256) quant_w_kernel(const float* __restrict__ w) {
    __shared__ float red[8];
    __shared__ float s_sh;
    const int o = blockIdx.x;
    const int t = threadIdx.x;

    const float4* wp = reinterpret_cast<const float4*>(w + (size_t)o * K_TOT + t * 16);
    float v[16];
#pragma unroll
    for (int i = 0; i < 4; ++i) {
        float4 f = wp[i];
        v[4*i+0] = f.x; v[4*i+1] = f.y; v[4*i+2] = f.z; v[4*i+3] = f.w;
    }

    float acc = 0.f;
#pragma unroll
    for (int i = 0; i < 16; ++i) acc += fabsf(v[i]);
#pragma unroll
    for (int d = 16; d > 0; d >>= 1) acc += __shfl_xor_sync(0xffffffffu, acc, d);
    if ((t & 31) == 0) red[t >> 5] = acc;
    __syncthreads();
    if (t == 0) {
        float tot = 0.f;
#pragma unroll
        for (int i = 0; i < 8; ++i) tot += red[i];
        float s = fmaxf(tot * (1.0f / 4096.0f), 1e-5f);
        s_sh = s;
        g_sw[o] = s;
    }
    __syncthreads();
    const float inv_s = 1.0f / s_sh;

    uint32_t p[8];
#pragma unroll
    for (int i = 0; i < 8; ++i) {
        float t0 = fminf(fmaxf(rintf(v[2*i+0] * inv_s), -1.f), 1.f);
        float t1 = fminf(fmaxf(rintf(v[2*i+1] * inv_s), -1.f), 1.f);
        __half2 h = __floats2half2_rn(t0, t1);
        p[i] = *reinterpret_cast<uint32_t*>(&h);
    }

    uint4* dst = reinterpret_cast<uint4*>(g_wt + (size_t)o * K_TOT + t * 16);
    dst[0] = make_uint4(p[0], p[1], p[2], p[3]);
    dst[1] = make_uint4(p[4], p[5], p[6], p[7]);
}

// ---------------------------------------------------------------------------
// Persistent GEMM: each CTA loops over 128M x 256N tiles. 4-stage cp.async
// ring runs CONTINUOUSLY across tiles (NK % STAGES == 0), so the next tile's
// first 3 k-tiles load during the current tile's last iterations and the
// epilogue overlaps the fill. 8 warps (2M x 4N), 64x64 each, mma.sync f16.
// smem swizzle: phys_chunk = c ^ ((row>>1)&3) within 64B rows.
// ---------------------------------------------------------------------------
__global__ void __launch_bounds__(256, 1) bitlinear_gemm(float* __restrict__ out) {
    extern __shared__ __align__(128) unsigned char smem[];
    const uint32_t sb = smem_u32(smem);
    const int tid  = threadIdx.x;
    const int lane = tid & 31;
    const int wid  = tid >> 5;
    const int warp_m = (wid & 1) * 64;
    const int warp_n = (wid >> 1) * 64;

    // per-thread loader offsets (A: 512 x 16B chunks, B: 1024)
    uint32_t a_sm[2]; size_t a_off[2];
#pragma unroll
    for (int i = 0; i < 2; ++i) {
        int idx = tid + 256 * i, r = idx >> 2, c = idx & 3;
        a_sm[i]  = r * 64 + ((c ^ ((r >> 1) & 3)) * 16);
        a_off[i] = (size_t)r * K_TOT + c * 8;
    }
    uint32_t b_sm[4]; size_t b_off[4];
#pragma unroll
    for (int i = 0; i < 4; ++i) {
        int idx = tid + 256 * i, r = idx >> 2, c = idx & 3;
        b_sm[i]  = A_STAGE + r * 64 + ((c ^ ((r >> 1) & 3)) * 16);
        b_off[i] = (size_t)r * K_TOT + c * 8;
    }

    // ldmatrix lane offsets (kk=0); kk=1 -> XOR 32
    const int rA = warp_m + (lane & 15);
    const uint32_t aoff = rA * 64 + ((((lane >> 4) & 1) ^ ((rA >> 1) & 3)) * 16);
    const int rB = warp_n + (lane & 7) + ((lane >> 4) << 3);
    const uint32_t boff = A_STAGE + rB * 64 + ((((lane >> 3) & 1) ^ ((rB >> 1) & 3)) * 16);

    int tile = blockIdx.x;
    const int stride = gridDim.x;

    const __half* gA = g_z  + (size_t)((tile >> 4) * TILE_M) * K_TOT;
    const __half* gB = g_wt + (size_t)((tile & 15) * TILE_N) * K_TOT;

    // prologue: first 3 k-tiles of first tile
#pragma unroll
    for (int s = 0; s < STAGES - 1; ++s) {
        const uint32_t base = sb + s * STAGE_BYTES;
#pragma unroll
        for (int i = 0; i < 2; ++i) cp_async16(base + a_sm[i], gA + a_off[i] + s * TILE_K);
#pragma unroll
        for (int i = 0; i < 4; ++i) cp_async16(base + b_sm[i], gB + b_off[i] + s * TILE_K);
        cp_commit();
    }

    while (tile < NTILES) {
        const int mt = tile >> 4, nt = tile & 15;
        const int tile_next = tile + stride;
        const __half* gA2 = nullptr; const __half* gB2 = nullptr;
        const bool has_next = tile_next < NTILES;
        if (has_next) {
            gA2 = g_z  + (size_t)((tile_next >> 4) * TILE_M) * K_TOT;
            gB2 = g_wt + (size_t)((tile_next & 15) * TILE_N) * K_TOT;
        }

        float acc[4][8][4];
#pragma unroll
        for (int i = 0; i < 4; ++i)
#pragma unroll
            for (int j = 0; j < 8; ++j)
#pragma unroll
                for (int e = 0; e < 4; ++e) acc[i][j][e] = 0.f;

        for (int kt = 0; kt < NK; ++kt) {
            cp_wait<STAGES - 2>();
            __syncthreads();

            // prefetch iteration kt+3 (this tile, or next tile's k-tile kt+3-NK)
            const int pf = kt + (STAGES - 1);
            const uint32_t pbase = sb + (pf & (STAGES - 1)) * STAGE_BYTES;
            if (pf < NK) {
#pragma unroll
                for (int i = 0; i < 2; ++i) cp_async16(pbase + a_sm[i], gA + a_off[i] + pf * TILE_K);
#pragma unroll
                for (int i = 0; i < 4; ++i) cp_async16(pbase + b_sm[i], gB + b_off[i] + pf * TILE_K);
            } else if (has_next) {
                const int pk = pf - NK;
#pragma unroll
                for (int i = 0; i < 2; ++i) cp_async16(pbase + a_sm[i], gA2 + a_off[i] + pk * TILE_K);
#pragma unroll
                for (int i = 0; i < 4; ++i) cp_async16(pbase + b_sm[i], gB2 + b_off[i] + pk * TILE_K);
            }
            cp_commit();

            const uint32_t sbase = sb + (kt & (STAGES - 1)) * STAGE_BYTES;
#pragma unroll
            for (int kk = 0; kk < 2; ++kk) {
                const uint32_t kx = kk << 5;
                uint32_t a[4][4], b[4][4];
#pragma unroll
                for (int i = 0; i < 4; ++i) ldsm4(a[i], (sbase + aoff + i * 1024) ^ kx);
#pragma unroll
                for (int j = 0; j < 4; ++j) ldsm4(b[j], (sbase + boff + j * 1024) ^ kx);
#pragma unroll
                for (int i = 0; i < 4; ++i)
#pragma unroll
                    for (int j = 0; j < 8; ++j) {
                        const uint32_t* bt = b[j >> 1];
                        mma16816(acc[i][j], a[i], bt[(j & 1) * 2], bt[(j & 1) * 2 + 1]);
                    }
            }
        }

        // epilogue (overlaps next tile's in-flight cp.asyncs)
        float swv[8][2];
#pragma unroll
        for (int j = 0; j < 8; ++j) {
            const int gcol = nt * TILE_N + warp_n + j * 8 + (lane & 3) * 2;
            swv[j][0] = __ldg(g_sw + gcol);
            swv[j][1] = __ldg(g_sw + gcol + 1);
        }
#pragma unroll
        for (int i = 0; i < 4; ++i) {
            const int r0 = mt * TILE_M + warp_m + i * 16 + (lane >> 2);
            float* o0 = out + (size_t)r0 * N_TOT + nt * TILE_N;
            float* o1 = o0 + 8 * N_TOT;
#pragma unroll
            for (int j = 0; j < 8; ++j) {
                const int col = warp_n + j * 8 + (lane & 3) * 2;
                float2 v0 = make_float2(acc[i][j][0] * swv[j][0], acc[i][j][1] * swv[j][1]);
                float2 v1 = make_float2(acc[i][j][2] * swv[j][0], acc[i][j][3] * swv[j][1]);
                *reinterpret_cast<float2*>(o0 + col) = v0;
                *reinterpret_cast<float2*>(o1 + col) = v1;
            }
        }

        tile = tile_next;
        gA = gA2; gB = gB2;
    }
}

// ---------------------------------------------------------------------------
// launch
// ---------------------------------------------------------------------------
extern "C" void kernel_launch(void* const* d_in, const int* in_sizes, int n_in,
                              void* d_out, int out_size) {
    (void)in_sizes; (void)n_in; (void)out_size;
    const float* x = (const float*)d_in[0];   // [4,2048,4096] fp32
    const float* w = (const float*)d_in[1];   // [4096,4096]   fp32
    float* out = (float*)d_out;               // [4,2048,4096] fp32

    quant_x_kernel<<<M_TOT, 256>>>(x);
    quant_w_kernel<<<N_TOT, 256>>>(w);

    static int nsm = 0;
    if (nsm == 0) {
        cudaDeviceGetAttribute(&nsm, cudaDevAttrMultiProcessorCount, 0);
        if (nsm <= 0) nsm = 148;
        cudaFuncSetAttribute(bitlinear_gemm,
                             cudaFuncAttributeMaxDynamicSharedMemorySize, SMEM_DYN);
    }
    bitlinear_gemm<<<nsm, 256, SMEM_DYN>>>(out);
}

// round 4
// speedup vs baseline: 1.1509x; 1.1509x over previous
#include <cuda_runtime.h>
#include <cuda_fp16.h>
#include <cstdint>

// ---------------------------------------------------------------------------
// BitLinear 1.58b on sm_103 (baseline PTX only):
//   y[m,o] = s_w[o] * sum_k z[m,k] * t[o,k]
//   z = absmax fake-quant of x (fp16), t = ternary weights {-1,0,1} (fp16)
// quant_x / quant_w -> pipelined cp.async + ldmatrix + mma.sync f16 GEMM
// (one 128x256 tile per CTA, TILE_K=64, 3 stages)
// ---------------------------------------------------------------------------

static constexpr int M_TOT = 8192;
static constexpr int K_TOT = 4096;
static constexpr int N_TOT = 4096;

static constexpr int TILE_M = 128;
static constexpr int TILE_N = 256;
static constexpr int TILE_K = 64;
static constexpr int NK     = K_TOT / TILE_K;   // 64
static constexpr int STAGES = 3;

static constexpr int A_STAGE = TILE_M * TILE_K * 2;      // 16384 B (128 rows x 128B)
static constexpr int B_STAGE = TILE_N * TILE_K * 2;      // 32768 B (256 rows x 128B)
static constexpr int STAGE_BYTES = A_STAGE + B_STAGE;    // 49152 B
static constexpr int SMEM_DYN = STAGES * STAGE_BYTES;    // 147456 B

__device__ __align__(16) __half g_z [(size_t)M_TOT * K_TOT];   // 64 MB
__device__ __align__(16) __half g_wt[(size_t)N_TOT * K_TOT];   // 32 MB
__device__ float g_sw[N_TOT];

// ---------------------------------------------------------------------------
__device__ __forceinline__ uint32_t smem_u32(const void* p) {
    uint32_t a;
    asm("{ .reg .u64 t; cvta.to.shared.u64 t, %1; cvt.u32.u64 %0, t; }" : "=r"(a) : "l"(p));
    return a;
}
__device__ __forceinline__ void cp_async16(uint32_t saddr, const void* g) {
    asm volatile("cp.async.cg.shared.global [%0], [%1], 16;" :: "r"(saddr), "l"(g) : "memory");
}
__device__ __forceinline__ void cp_commit() {
    asm volatile("cp.async.commit_group;" ::: "memory");
}
template<int N> __device__ __forceinline__ void cp_wait() {
    asm volatile("cp.async.wait_group %0;" :: "n"(N) : "memory");
}
__device__ __forceinline__ void ldsm4(uint32_t* r, uint32_t addr) {
    asm volatile("ldmatrix.sync.aligned.m8n8.x4.shared.b16 {%0,%1,%2,%3}, [%4];"
                 : "=r"(r[0]), "=r"(r[1]), "=r"(r[2]), "=r"(r[3]) : "r"(addr));
}
__device__ __forceinline__ void mma16816(float* c, const uint32_t* a, uint32_t b0, uint32_t b1) {
    asm volatile(
        "mma.sync.aligned.m16n8k16.row.col.f32.f16.f16.f32 "
        "{%0,%1,%2,%3}, {%4,%5,%6,%7}, {%8,%9}, {%0,%1,%2,%3};"
        : "+f"(c[0]), "+f"(c[1]), "+f"(c[2]), "+f"(c[3])
        : "r"(a[0]), "r"(a[1]), "r"(a[2]), "r"(a[3]), "r"(b0), "r"(b1));
}

// ---------------------------------------------------------------------------
// quantize x: per-token groups of 64, absmax fake-quant -> fp16 row-major
// ---------------------------------------------------------------------------
__global__ void __launch_bounds__(256) quant_x_kernel(const float* __restrict__ x) {
    const int m = blockIdx.x;
    const int t = threadIdx.x;

    const float4* xp = reinterpret_cast<const float4*>(x + (size_t)m * K_TOT + t * 16);
    float v[16];
#pragma unroll
    for (int i = 0; i < 4; ++i) {
        float4 f = xp[i];
        v[4*i+0] = f.x; v[4*i+1] = f.y; v[4*i+2] = f.z; v[4*i+3] = f.w;
    }

    float am = 0.f;
#pragma unroll
    for (int i = 0; i < 16; ++i) am = fmaxf(am, fabsf(v[i]));
    am = fmaxf(am, __shfl_xor_sync(0xffffffffu, am, 1));
    am = fmaxf(am, __shfl_xor_sync(0xffffffffu, am, 2));
    am = fmaxf(am, 1e-5f);
    const float scale = 127.0f / am;
    const float inv   = am * (1.0f / 127.0f);

    uint32_t p[8];
#pragma unroll
    for (int i = 0; i < 8; ++i) {
        float q0 = fminf(fmaxf(rintf(v[2*i+0] * scale), -127.f), 127.f) * inv;
        float q1 = fminf(fmaxf(rintf(v[2*i+1] * scale), -127.f), 127.f) * inv;
        __half2 h = __floats2half2_rn(q0, q1);
        p[i] = *reinterpret_cast<uint32_t*>(&h);
    }

    uint4* dst = reinterpret_cast<uint4*>(g_z + (size_t)m * K_TOT + t * 16);
    dst[0] = make_uint4(p[0], p[1], p[2], p[3]);
    dst[1] = make_uint4(p[4], p[5], p[6], p[7]);
}

// ---------------------------------------------------------------------------
// quantize w: per-row absmean ternary -> fp16 {-1,0,1}; s_w fp32
// ---------------------------------------------------------------------------
__global__ void __launch_bounds__(256) quant_w_kernel(const float* __restrict__ w) {
    __shared__ float red[8];
    __shared__ float s_sh;
    const int o = blockIdx.x;
    const int t = threadIdx.x;

    const float4* wp = reinterpret_cast<const float4*>(w + (size_t)o * K_TOT + t * 16);
    float v[16];
#pragma unroll
    for (int i = 0; i < 4; ++i) {
        float4 f = wp[i];
        v[4*i+0] = f.x; v[4*i+1] = f.y; v[4*i+2] = f.z; v[4*i+3] = f.w;
    }

    float acc = 0.f;
#pragma unroll
    for (int i = 0; i < 16; ++i) acc += fabsf(v[i]);
#pragma unroll
    for (int d = 16; d > 0; d >>= 1) acc += __shfl_xor_sync(0xffffffffu, acc, d);
    if ((t & 31) == 0) red[t >> 5] = acc;
    __syncthreads();
    if (t == 0) {
        float tot = 0.f;
#pragma unroll
        for (int i = 0; i < 8; ++i) tot += red[i];
        float s = fmaxf(tot * (1.0f / 4096.0f), 1e-5f);
        s_sh = s;
        g_sw[o] = s;
    }
    __syncthreads();
    const float inv_s = 1.0f / s_sh;

    uint32_t p[8];
#pragma unroll
    for (int i = 0; i < 8; ++i) {
        float t0 = fminf(fmaxf(rintf(v[2*i+0] * inv_s), -1.f), 1.f);
        float t1 = fminf(fmaxf(rintf(v[2*i+1] * inv_s), -1.f), 1.f);
        __half2 h = __floats2half2_rn(t0, t1);
        p[i] = *reinterpret_cast<uint32_t*>(&h);
    }

    uint4* dst = reinterpret_cast<uint4*>(g_wt + (size_t)o * K_TOT + t * 16);
    dst[0] = make_uint4(p[0], p[1], p[2], p[3]);
    dst[1] = make_uint4(p[4], p[5], p[6], p[7]);
}

// ---------------------------------------------------------------------------
// GEMM: 128M x 256N per CTA, K-step 64, 3-stage cp.async pipeline, mma.sync.
// 8 warps (2M x 4N), each 64x64. Smem rows are 128B (8 x 16B chunks) with
// swizzle phys_chunk = c ^ (row & 7); MMA k-step s addressed via XOR (s<<5).
// ---------------------------------------------------------------------------
__global__ void __launch_bounds__(256, 1) bitlinear_gemm(float* __restrict__ out) {
    extern __shared__ __align__(128) unsigned char smem[];
    const uint32_t sb = smem_u32(smem);
    const int tid  = threadIdx.x;
    const int lane = tid & 31;
    const int wid  = tid >> 5;
    const int nt = blockIdx.x;   // 0..15
    const int mt = blockIdx.y;   // 0..63
    const int warp_m = (wid & 1) * 64;
    const int warp_n = (wid >> 1) * 64;

    const __half* gA = g_z  + (size_t)(mt * TILE_M) * K_TOT;
    const __half* gB = g_wt + (size_t)(nt * TILE_N) * K_TOT;

    // loader offsets: A = 1024 chunks of 16B (4/thread), B = 2048 (8/thread)
    uint32_t a_sm[4]; size_t a_off[4];
#pragma unroll
    for (int i = 0; i < 4; ++i) {
        int idx = tid + 256 * i, r = idx >> 3, c = idx & 7;
        a_sm[i]  = r * 128 + ((c ^ (r & 7)) * 16);
        a_off[i] = (size_t)r * K_TOT + c * 8;
    }
    uint32_t b_sm[8]; size_t b_off[8];
#pragma unroll
    for (int i = 0; i < 8; ++i) {
        int idx = tid + 256 * i, r = idx >> 3, c = idx & 7;
        b_sm[i]  = A_STAGE + r * 128 + ((c ^ (r & 7)) * 16);
        b_off[i] = (size_t)r * K_TOT + c * 8;
    }

    // ldmatrix base offsets (k-step 0); step s -> XOR (s<<5)
    const int rA = warp_m + (lane & 15);
    const uint32_t aoff = rA * 128 + ((((lane >> 4) & 1) ^ (rA & 7)) * 16);
    const int rB = warp_n + (lane & 7) + ((lane >> 4) << 3);
    const uint32_t boff = A_STAGE + rB * 128 + ((((lane >> 3) & 1) ^ (rB & 7)) * 16);

    float acc[4][8][4];
#pragma unroll
    for (int i = 0; i < 4; ++i)
#pragma unroll
        for (int j = 0; j < 8; ++j)
#pragma unroll
            for (int e = 0; e < 4; ++e) acc[i][j][e] = 0.f;

    // prologue: prefetch 2 k-tiles
#pragma unroll
    for (int s = 0; s < STAGES - 1; ++s) {
        const uint32_t base = sb + s * STAGE_BYTES;
#pragma unroll
        for (int i = 0; i < 4; ++i) cp_async16(base + a_sm[i], gA + a_off[i] + s * TILE_K);
#pragma unroll
        for (int i = 0; i < 8; ++i) cp_async16(base + b_sm[i], gB + b_off[i] + s * TILE_K);
        cp_commit();
    }

    for (int kt = 0; kt < NK; ++kt) {
        cp_wait<STAGES - 2>();
        __syncthreads();

        // prefetch k-tile kt+2 into stage (kt+2)%3 (consumed at kt-1; the
        // syncthreads above makes that consumption visible to all threads)
        if (kt + STAGES - 1 < NK) {
            const int kn = kt + STAGES - 1;
            const uint32_t base = sb + ((kt + STAGES - 1) % STAGES) * STAGE_BYTES;
#pragma unroll
            for (int i = 0; i < 4; ++i) cp_async16(base + a_sm[i], gA + a_off[i] + kn * TILE_K);
#pragma unroll
            for (int i = 0; i < 8; ++i) cp_async16(base + b_sm[i], gB + b_off[i] + kn * TILE_K);
        }
        cp_commit();

        const uint32_t sbase = sb + (kt % STAGES) * STAGE_BYTES;
#pragma unroll
        for (int s = 0; s < 4; ++s) {
            const uint32_t kx = s << 5;
            uint32_t a[4][4], b[4][4];
#pragma unroll
            for (int i = 0; i < 4; ++i) ldsm4(a[i], (sbase + aoff + i * 2048) ^ kx);
#pragma unroll
            for (int j = 0; j < 4; ++j) ldsm4(b[j], (sbase + boff + j * 2048) ^ kx);
#pragma unroll
            for (int i = 0; i < 4; ++i)
#pragma unroll
                for (int j = 0; j < 8; ++j) {
                    const uint32_t* bt = b[j >> 1];
                    mma16816(acc[i][j], a[i], bt[(j & 1) * 2], bt[(j & 1) * 2 + 1]);
                }
        }
    }

    // --- epilogue: scale by s_w[n], write fp32 ---
    float swv[8][2];
#pragma unroll
    for (int j = 0; j < 8; ++j) {
        const int gcol = nt * TILE_N + warp_n + j * 8 + (lane & 3) * 2;
        swv[j][0] = __ldg(g_sw + gcol);
        swv[j][1] = __ldg(g_sw + gcol + 1);
    }
#pragma unroll
    for (int i = 0; i < 4; ++i) {
        const int r0 = mt * TILE_M + warp_m + i * 16 + (lane >> 2);
        float* o0 = out + (size_t)r0 * N_TOT + nt * TILE_N;
        float* o1 = o0 + 8 * N_TOT;
#pragma unroll
        for (int j = 0; j < 8; ++j) {
            const int col = warp_n + j * 8 + (lane & 3) * 2;
            float2 v0 = make_float2(acc[i][j][0] * swv[j][0], acc[i][j][1] * swv[j][1]);
            float2 v1 = make_float2(acc[i][j][2] * swv[j][0], acc[i][j][3] * swv[j][1]);
            *reinterpret_cast<float2*>(o0 + col) = v0;
            *reinterpret_cast<float2*>(o1 + col) = v1;
        }
    }
}

// ---------------------------------------------------------------------------
// launch
// ---------------------------------------------------------------------------
extern "C" void kernel_launch(void* const* d_in, const int* in_sizes, int n_in,
                              void* d_out, int out_size) {
    (void)in_sizes; (void)n_in; (void)out_size;
    const float* x = (const float*)d_in[0];   // [4,2048,4096] fp32
    const float* w = (const float*)d_in[1];   // [4096,4096]   fp32
    float* out = (float*)d_out;               // [4,2048,4096] fp32

    quant_x_kernel<<<M_TOT, 256>>>(x);
    quant_w_kernel<<<N_TOT, 256>>>(w);

    static bool attr_set = false;
    if (!attr_set) {
        cudaFuncSetAttribute(bitlinear_gemm,
                             cudaFuncAttributeMaxDynamicSharedMemorySize, SMEM_DYN);
        attr_set = true;
    }
    dim3 grid(N_TOT / TILE_N, M_TOT / TILE_M);   // (16, 64)
    bitlinear_gemm<<<grid, 256, SMEM_DYN>>>(out);
}

// round 5
// speedup vs baseline: 1.2311x; 1.0698x over previous
#include <cuda_runtime.h>
#include <cuda_fp16.h>
#include <cstdint>

// ---------------------------------------------------------------------------
// BitLinear 1.58b on sm_103 (baseline PTX only):
//   y[m,o] = s_w[o] * sum_k z[m,k] * t[o,k]
//   z = absmax fake-quant of x (fp16), t = ternary weights {-1,0,1} (fp16)
// quant_x / quant_w -> pipelined cp.async + ldmatrix + mma.sync f16 GEMM
// (round-2 structure: 128x256 tile/CTA, TILE_K=32, 4 stages, prefetch AFTER
//  compute; this round: all LDSMs hoisted ahead of both MMA phases + .cs
//  epilogue stores)
// ---------------------------------------------------------------------------

static constexpr int M_TOT = 8192;
static constexpr int K_TOT = 4096;
static constexpr int N_TOT = 4096;

static constexpr int TILE_M = 128;
static constexpr int TILE_N = 256;
static constexpr int TILE_K = 32;
static constexpr int NK     = K_TOT / TILE_K;   // 128
static constexpr int STAGES = 4;

static constexpr int A_STAGE = TILE_M * TILE_K * 2;      // 8192 B
static constexpr int B_STAGE = TILE_N * TILE_K * 2;      // 16384 B
static constexpr int STAGE_BYTES = A_STAGE + B_STAGE;    // 24576 B
static constexpr int SMEM_DYN = STAGES * STAGE_BYTES;    // 98304 B

__device__ __align__(16) __half g_z [(size_t)M_TOT * K_TOT];   // 64 MB
__device__ __align__(16) __half g_wt[(size_t)N_TOT * K_TOT];   // 32 MB
__device__ float g_sw[N_TOT];

// ---------------------------------------------------------------------------
__device__ __forceinline__ uint32_t smem_u32(const void* p) {
    uint32_t a;
    asm("{ .reg .u64 t; cvta.to.shared.u64 t, %1; cvt.u32.u64 %0, t; }" : "=r"(a) : "l"(p));
    return a;
}
__device__ __forceinline__ void cp_async16(uint32_t saddr, const void* g) {
    asm volatile("cp.async.cg.shared.global [%0], [%1], 16;" :: "r"(saddr), "l"(g) : "memory");
}
__device__ __forceinline__ void cp_commit() {
    asm volatile("cp.async.commit_group;" ::: "memory");
}
template<int N> __device__ __forceinline__ void cp_wait() {
    asm volatile("cp.async.wait_group %0;" :: "n"(N) : "memory");
}
__device__ __forceinline__ void ldsm4(uint32_t* r, uint32_t addr) {
    asm volatile("ldmatrix.sync.aligned.m8n8.x4.shared.b16 {%0,%1,%2,%3}, [%4];"
                 : "=r"(r[0]), "=r"(r[1]), "=r"(r[2]), "=r"(r[3]) : "r"(addr));
}
__device__ __forceinline__ void mma16816(float* c, const uint32_t* a, uint32_t b0, uint32_t b1) {
    asm volatile(
        "mma.sync.aligned.m16n8k16.row.col.f32.f16.f16.f32 "
        "{%0,%1,%2,%3}, {%4,%5,%6,%7}, {%8,%9}, {%0,%1,%2,%3};"
        : "+f"(c[0]), "+f"(c[1]), "+f"(c[2]), "+f"(c[3])
        : "r"(a[0]), "r"(a[1]), "r"(a[2]), "r"(a[3]), "r"(b0), "r"(b1));
}

// ---------------------------------------------------------------------------
// quantize x: per-token groups of 64, absmax fake-quant -> fp16 row-major
// ---------------------------------------------------------------------------
__global__ void __launch_bounds__(256) quant_x_kernel(const float* __restrict__ x) {
    const int m = blockIdx.x;
    const int t = threadIdx.x;

    const float4* xp = reinterpret_cast<const float4*>(x + (size_t)m * K_TOT + t * 16);
    float v[16];
#pragma unroll
    for (int i = 0; i < 4; ++i) {
        float4 f = xp[i];
        v[4*i+0] = f.x; v[4*i+1] = f.y; v[4*i+2] = f.z; v[4*i+3] = f.w;
    }

    float am = 0.f;
#pragma unroll
    for (int i = 0; i < 16; ++i) am = fmaxf(am, fabsf(v[i]));
    am = fmaxf(am, __shfl_xor_sync(0xffffffffu, am, 1));
    am = fmaxf(am, __shfl_xor_sync(0xffffffffu, am, 2));
    am = fmaxf(am, 1e-5f);
    const float scale = 127.0f / am;
    const float inv   = am * (1.0f / 127.0f);

    uint32_t p[8];
#pragma unroll
    for (int i = 0; i < 8; ++i) {
        float q0 = fminf(fmaxf(rintf(v[2*i+0] * scale), -127.f), 127.f) * inv;
        float q1 = fminf(fmaxf(rintf(v[2*i+1] * scale), -127.f), 127.f) * inv;
        __half2 h = __floats2half2_rn(q0, q1);
        p[i] = *reinterpret_cast<uint32_t*>(&h);
    }

    uint4* dst = reinterpret_cast<uint4*>(g_z + (size_t)m * K_TOT + t * 16);
    dst[0] = make_uint4(p[0], p[1], p[2], p[3]);
    dst[1] = make_uint4(p[4], p[5], p[6], p[7]);
}

// ---------------------------------------------------------------------------
// quantize w: per-row absmean ternary -> fp16 {-1,0,1}; s_w fp32
// ---------------------------------------------------------------------------
__global__ void __launch_bounds__(256) quant_w_kernel(const float* __restrict__ w) {
    __shared__ float red[8];
    __shared__ float s_sh;
    const int o = blockIdx.x;
    const int t = threadIdx.x;

    const float4* wp = reinterpret_cast<const float4*>(w + (size_t)o * K_TOT + t * 16);
    float v[16];
#pragma unroll
    for (int i = 0; i < 4; ++i) {
        float4 f = wp[i];
        v[4*i+0] = f.x; v[4*i+1] = f.y; v[4*i+2] = f.z; v[4*i+3] = f.w;
    }

    float acc = 0.f;
#pragma unroll
    for (int i = 0; i < 16; ++i) acc += fabsf(v[i]);
#pragma unroll
    for (int d = 16; d > 0; d >>= 1) acc += __shfl_xor_sync(0xffffffffu, acc, d);
    if ((t & 31) == 0) red[t >> 5] = acc;
    __syncthreads();
    if (t == 0) {
        float tot = 0.f;
#pragma unroll
        for (int i = 0; i < 8; ++i) tot += red[i];
        float s = fmaxf(tot * (1.0f / 4096.0f), 1e-5f);
        s_sh = s;
        g_sw[o] = s;
    }
    __syncthreads();
    const float inv_s = 1.0f / s_sh;

    uint32_t p[8];
#pragma unroll
    for (int i = 0; i < 8; ++i) {
        float t0 = fminf(fmaxf(rintf(v[2*i+0] * inv_s), -1.f), 1.f);
        float t1 = fminf(fmaxf(rintf(v[2*i+1] * inv_s), -1.f), 1.f);
        __half2 h = __floats2half2_rn(t0, t1);
        p[i] = *reinterpret_cast<uint32_t*>(&h);
    }

    uint4* dst = reinterpret_cast<uint4*>(g_wt + (size_t)o * K_TOT + t * 16);
    dst[0] = make_uint4(p[0], p[1], p[2], p[3]);
    dst[1] = make_uint4(p[4], p[5], p[6], p[7]);
}

// ---------------------------------------------------------------------------
// GEMM: 128M x 256N per CTA, K-step 32, 4-stage cp.async pipeline, mma.sync.
// 8 warps (2M x 4N), each computes 64x64.
// smem swizzle: within a 64B row (4 x 16B chunks), phys_chunk = c ^ ((row>>1)&3)
// Inner loop: ALL ldmatrix (both k-phases) issue first, then both MMA phases,
// then prefetch+commit (known-good r2 position).
// ---------------------------------------------------------------------------
__global__ void __launch_bounds__(256, 1) bitlinear_gemm(float* __restrict__ out) {
    extern __shared__ __align__(128) unsigned char smem[];
    const uint32_t sb = smem_u32(smem);
    const int tid  = threadIdx.x;
    const int lane = tid & 31;
    const int wid  = tid >> 5;
    const int nt = blockIdx.x;   // 0..15
    const int mt = blockIdx.y;   // 0..63
    const int warp_m = (wid & 1) * 64;
    const int warp_n = (wid >> 1) * 64;

    const __half* gA = g_z  + (size_t)(mt * TILE_M) * K_TOT;
    const __half* gB = g_wt + (size_t)(nt * TILE_N) * K_TOT;

    // --- loader task precompute (A: 512 x 16B chunks, B: 1024) ---
    uint32_t a_sm[2]; size_t a_off[2];
#pragma unroll
    for (int i = 0; i < 2; ++i) {
        int idx = tid + 256 * i, r = idx >> 2, c = idx & 3;
        a_sm[i]  = r * 64 + ((c ^ ((r >> 1) & 3)) * 16);
        a_off[i] = (size_t)r * K_TOT + c * 8;
    }
    uint32_t b_sm[4]; size_t b_off[4];
#pragma unroll
    for (int i = 0; i < 4; ++i) {
        int idx = tid + 256 * i, r = idx >> 2, c = idx & 3;
        b_sm[i]  = A_STAGE + r * 64 + ((c ^ ((r >> 1) & 3)) * 16);
        b_off[i] = (size_t)r * K_TOT + c * 8;
    }

    // --- ldmatrix lane address offsets (kk=0); kk=1 -> XOR 32 ---
    const int rA = warp_m + (lane & 15);
    const uint32_t aoff = rA * 64 + ((((lane >> 4) & 1) ^ ((rA >> 1) & 3)) * 16);
    const int rB = warp_n + (lane & 7) + ((lane >> 4) << 3);
    const uint32_t boff = A_STAGE + rB * 64 + ((((lane >> 3) & 1) ^ ((rB >> 1) & 3)) * 16);

    float acc[4][8][4];
#pragma unroll
    for (int i = 0; i < 4; ++i)
#pragma unroll
        for (int j = 0; j < 8; ++j)
#pragma unroll
            for (int e = 0; e < 4; ++e) acc[i][j][e] = 0.f;

    // prologue: prefetch 3 k-tiles
#pragma unroll
    for (int s = 0; s < STAGES - 1; ++s) {
        uint32_t base = sb + s * STAGE_BYTES;
#pragma unroll
        for (int i = 0; i < 2; ++i) cp_async16(base + a_sm[i], gA + a_off[i] + s * TILE_K);
#pragma unroll
        for (int i = 0; i < 4; ++i) cp_async16(base + b_sm[i], gB + b_off[i] + s * TILE_K);
        cp_commit();
    }

    for (int kt = 0; kt < NK; ++kt) {
        cp_wait<STAGES - 2>();
        __syncthreads();

        const uint32_t sbase = sb + (kt & (STAGES - 1)) * STAGE_BYTES;

        // issue ALL ldmatrix for both k-phases up front (LSU pipelines them;
        // MMA phase 0 waits only on the first batch, phase 1 latency hidden)
        uint32_t a0[4][4], b0[4][4], a1[4][4], b1[4][4];
#pragma unroll
        for (int i = 0; i < 4; ++i) ldsm4(a0[i], sbase + aoff + i * 1024);
#pragma unroll
        for (int j = 0; j < 4; ++j) ldsm4(b0[j], sbase + boff + j * 1024);
#pragma unroll
        for (int i = 0; i < 4; ++i) ldsm4(a1[i], (sbase + aoff + i * 1024) ^ 32);
#pragma unroll
        for (int j = 0; j < 4; ++j) ldsm4(b1[j], (sbase + boff + j * 1024) ^ 32);

#pragma unroll
        for (int i = 0; i < 4; ++i)
#pragma unroll
            for (int j = 0; j < 8; ++j) {
                const uint32_t* bt = b0[j >> 1];
                mma16816(acc[i][j], a0[i], bt[(j & 1) * 2], bt[(j & 1) * 2 + 1]);
            }
#pragma unroll
        for (int i = 0; i < 4; ++i)
#pragma unroll
            for (int j = 0; j < 8; ++j) {
                const uint32_t* bt = b1[j >> 1];
                mma16816(acc[i][j], a1[i], bt[(j & 1) * 2], bt[(j & 1) * 2 + 1]);
            }

        // prefetch k-tile kt+3 into stage (kt+3)%4 (fully consumed at kt-1;
        // the __syncthreads above makes that visible to all threads)
        if (kt + STAGES - 1 < NK) {
            const int kn = kt + STAGES - 1;
            uint32_t base = sb + (kn & (STAGES - 1)) * STAGE_BYTES;
#pragma unroll
            for (int i = 0; i < 2; ++i) cp_async16(base + a_sm[i], gA + a_off[i] + kn * TILE_K);
#pragma unroll
            for (int i = 0; i < 4; ++i) cp_async16(base + b_sm[i], gB + b_off[i] + kn * TILE_K);
        }
        cp_commit();
    }

    // --- epilogue: scale by s_w[n], write fp32 with evict-first hint ---
    float swv[8][2];
#pragma unroll
    for (int j = 0; j < 8; ++j) {
        const int gcol = nt * TILE_N + warp_n + j * 8 + (lane & 3) * 2;
        swv[j][0] = __ldg(g_sw + gcol);
        swv[j][1] = __ldg(g_sw + gcol + 1);
    }
#pragma unroll
    for (int i = 0; i < 4; ++i) {
        const int r0 = mt * TILE_M + warp_m + i * 16 + (lane >> 2);
        float* o0 = out + (size_t)r0 * N_TOT + nt * TILE_N;
        float* o1 = o0 + 8 * N_TOT;
#pragma unroll
        for (int j = 0; j < 8; ++j) {
            const int col = warp_n + j * 8 + (lane & 3) * 2;
            float2 v0 = make_float2(acc[i][j][0] * swv[j][0], acc[i][j][1] * swv[j][1]);
            float2 v1 = make_float2(acc[i][j][2] * swv[j][0], acc[i][j][3] * swv[j][1]);
            __stcs(reinterpret_cast<float2*>(o0 + col), v0);
            __stcs(reinterpret_cast<float2*>(o1 + col), v1);
        }
    }
}

// ---------------------------------------------------------------------------
// launch
// ---------------------------------------------------------------------------
extern "C" void kernel_launch(void* const* d_in, const int* in_sizes, int n_in,
                              void* d_out, int out_size) {
    (void)in_sizes; (void)n_in; (void)out_size;
    const float* x = (const float*)d_in[0];   // [4,2048,4096] fp32
    const float* w = (const float*)d_in[1];   // [4096,4096]   fp32
    float* out = (float*)d_out;               // [4,2048,4096] fp32

    quant_x_kernel<<<M_TOT, 256>>>(x);
    quant_w_kernel<<<N_TOT, 256>>>(w);

    static bool attr_set = false;
    if (!attr_set) {
        cudaFuncSetAttribute(bitlinear_gemm,
                             cudaFuncAttributeMaxDynamicSharedMemorySize, SMEM_DYN);
        attr_set = true;
    }
    dim3 grid(N_TOT / TILE_N, M_TOT / TILE_M);   // (16, 64)
    bitlinear_gemm<<<grid, 256, SMEM_DYN>>>(out);
}

// round 11
// speedup vs baseline: 1.2601x; 1.0235x over previous
#include <cuda_runtime.h>
#include <cuda_fp16.h>
#include <cstdint>

// ---------------------------------------------------------------------------
// BitLinear 1.58b on sm_103 (baseline PTX only — no tcgen05 / 'a' features):
//   y[m,o] = s_w[o] * sum_k z[m,k] * t[o,k]
//   z = absmax fake-quant of x (fp16), t = ternary weights {-1,0,1} (fp16)
// quant_x / quant_w -> pipelined cp.async + ldmatrix + mma.sync f16 GEMM
// TRUE round-2 source (641.9us validated pass), restored verbatim.
// r10's "revert" accidentally carried an OOB write s_sw[tid+128] (s_sw has
// only 256 entries, blockDim=256) introduced in r7 — removed here.
// ---------------------------------------------------------------------------

static constexpr int M_TOT = 8192;
static constexpr int K_TOT = 4096;
static constexpr int N_TOT = 4096;

static constexpr int TILE_M = 128;
static constexpr int TILE_N = 256;
static constexpr int TILE_K = 32;
static constexpr int NK     = K_TOT / TILE_K;   // 128
static constexpr int STAGES = 4;

static constexpr int A_STAGE = TILE_M * TILE_K * 2;      // 8192 B
static constexpr int B_STAGE = TILE_N * TILE_K * 2;      // 16384 B
static constexpr int STAGE_BYTES = A_STAGE + B_STAGE;    // 24576 B
static constexpr int SMEM_DYN = STAGES * STAGE_BYTES;    // 98304 B

// scratch: quantized operands (module-scope device memory, no allocs)
__device__ __align__(16) __half g_z [(size_t)M_TOT * K_TOT];   // 64 MB
__device__ __align__(16) __half g_wt[(size_t)N_TOT * K_TOT];   // 32 MB
__device__ float g_sw[N_TOT];

// ---------------------------------------------------------------------------
// PTX helpers (all baseline sm_80/sm_90 features)
// ---------------------------------------------------------------------------
__device__ __forceinline__ uint32_t smem_u32(const void* p) {
    uint32_t a;
    asm("{ .reg .u64 t; cvta.to.shared.u64 t, %1; cvt.u32.u64 %0, t; }" : "=r"(a) : "l"(p));
    return a;
}
__device__ __forceinline__ void cp_async16(uint32_t saddr, const void* g) {
    asm volatile("cp.async.cg.shared.global [%0], [%1], 16;" :: "r"(saddr), "l"(g) : "memory");
}
__device__ __forceinline__ void cp_commit() {
    asm volatile("cp.async.commit_group;" ::: "memory");
}
template<int N> __device__ __forceinline__ void cp_wait() {
    asm volatile("cp.async.wait_group %0;" :: "n"(N) : "memory");
}
__device__ __forceinline__ void ldsm4(uint32_t* r, uint32_t addr) {
    asm volatile("ldmatrix.sync.aligned.m8n8.x4.shared.b16 {%0,%1,%2,%3}, [%4];"
                 : "=r"(r[0]), "=r"(r[1]), "=r"(r[2]), "=r"(r[3]) : "r"(addr));
}
__device__ __forceinline__ void mma16816(float* c, const uint32_t* a, uint32_t b0, uint32_t b1) {
    asm volatile(
        "mma.sync.aligned.m16n8k16.row.col.f32.f16.f16.f32 "
        "{%0,%1,%2,%3}, {%4,%5,%6,%7}, {%8,%9}, {%0,%1,%2,%3};"
        : "+f"(c[0]), "+f"(c[1]), "+f"(c[2]), "+f"(c[3])
        : "r"(a[0]), "r"(a[1]), "r"(a[2]), "r"(a[3]), "r"(b0), "r"(b1));
}

// ---------------------------------------------------------------------------
// quantize x: per-token groups of 64, absmax fake-quant -> fp16 row-major
// grid = 8192 blocks x 256 threads; thread t handles 16 contiguous k
// ---------------------------------------------------------------------------
__global__ void __launch_bounds__(256) quant_x_kernel(const float* __restrict__ x) {
    const int m = blockIdx.x;
    const int t = threadIdx.x;

    const float4* xp = reinterpret_cast<const float4*>(x + (size_t)m * K_TOT + t * 16);
    float v[16];
#pragma unroll
    for (int i = 0; i < 4; ++i) {
        float4 f = xp[i];
        v[4*i+0] = f.x; v[4*i+1] = f.y; v[4*i+2] = f.z; v[4*i+3] = f.w;
    }

    float am = 0.f;
#pragma unroll
    for (int i = 0; i < 16; ++i) am = fmaxf(am, fabsf(v[i]));
    // group of 64 elems = 4 consecutive lanes (quad-aligned)
    am = fmaxf(am, __shfl_xor_sync(0xffffffffu, am, 1));
    am = fmaxf(am, __shfl_xor_sync(0xffffffffu, am, 2));
    am = fmaxf(am, 1e-5f);
    const float scale = 127.0f / am;
    const float inv   = am * (1.0f / 127.0f);

    uint32_t p[8];
#pragma unroll
    for (int i = 0; i < 8; ++i) {
        float q0 = fminf(fmaxf(rintf(v[2*i+0] * scale), -127.f), 127.f) * inv;
        float q1 = fminf(fmaxf(rintf(v[2*i+1] * scale), -127.f), 127.f) * inv;
        __half2 h = __floats2half2_rn(q0, q1);
        p[i] = *reinterpret_cast<uint32_t*>(&h);
    }

    uint4* dst = reinterpret_cast<uint4*>(g_z + (size_t)m * K_TOT + t * 16);
    dst[0] = make_uint4(p[0], p[1], p[2], p[3]);
    dst[1] = make_uint4(p[4], p[5], p[6], p[7]);
}

// ---------------------------------------------------------------------------
// quantize w: per-row absmean ternary -> fp16 {-1,0,1} row-major; s_w fp32
// ---------------------------------------------------------------------------
__global__ void __launch_bounds__(256) quant_w_kernel(const float* __restrict__ w) {
    __shared__ float red[8];
    __shared__ float s_sh;
    const int o = blockIdx.x;
    const int t = threadIdx.x;

    const float4* wp = reinterpret_cast<const float4*>(w + (size_t)o * K_TOT + t * 16);
    float v[16];
#pragma unroll
    for (int i = 0; i < 4; ++i) {
        float4 f = wp[i];
        v[4*i+0] = f.x; v[4*i+1] = f.y; v[4*i+2] = f.z; v[4*i+3] = f.w;
    }

    float acc = 0.f;
#pragma unroll
    for (int i = 0; i < 16; ++i) acc += fabsf(v[i]);
#pragma unroll
    for (int d = 16; d > 0; d >>= 1) acc += __shfl_xor_sync(0xffffffffu, acc, d);
    if ((t & 31) == 0) red[t >> 5] = acc;
    __syncthreads();
    if (t == 0) {
        float tot = 0.f;
#pragma unroll
        for (int i = 0; i < 8; ++i) tot += red[i];
        float s = fmaxf(tot * (1.0f / 4096.0f), 1e-5f);
        s_sh = s;
        g_sw[o] = s;
    }
    __syncthreads();
    const float inv_s = 1.0f / s_sh;

    uint32_t p[8];
#pragma unroll
    for (int i = 0; i < 8; ++i) {
        float t0 = fminf(fmaxf(rintf(v[2*i+0] * inv_s), -1.f), 1.f);
        float t1 = fminf(fmaxf(rintf(v[2*i+1] * inv_s), -1.f), 1.f);
        __half2 h = __floats2half2_rn(t0, t1);
        p[i] = *reinterpret_cast<uint32_t*>(&h);
    }

    uint4* dst = reinterpret_cast<uint4*>(g_wt + (size_t)o * K_TOT + t * 16);
    dst[0] = make_uint4(p[0], p[1], p[2], p[3]);
    dst[1] = make_uint4(p[4], p[5], p[6], p[7]);
}

// ---------------------------------------------------------------------------
// GEMM: 128M x 256N per CTA, K-step 32, 4-stage cp.async pipeline, mma.sync.
// 8 warps (2M x 4N), each computes 64x64.
// smem swizzle: within a 64B row (4 x 16B chunks), phys_chunk = c ^ ((row>>1)&3)
//   -> 8-row ldmatrix phases touch 8 distinct 16B granules (conflict-free).
// ---------------------------------------------------------------------------
__global__ void __launch_bounds__(256, 1) bitlinear_gemm(float* __restrict__ out) {
    extern __shared__ __align__(128) unsigned char smem[];
    __shared__ float s_sw[TILE_N];
    const uint32_t sb = smem_u32(smem);
    const int tid  = threadIdx.x;
    const int lane = tid & 31;
    const int wid  = tid >> 5;
    const int nt = blockIdx.x;   // 0..15
    const int mt = blockIdx.y;   // 0..63
    const int warp_m = (wid & 1) * 64;
    const int warp_n = (wid >> 1) * 64;

    s_sw[tid] = g_sw[nt * TILE_N + tid];

    const __half* gA = g_z  + (size_t)(mt * TILE_M) * K_TOT;
    const __half* gB = g_wt + (size_t)(nt * TILE_N) * K_TOT;

    // --- loader task precompute (A: 512 x 16B chunks, B: 1024) ---
    uint32_t a_sm[2]; const __half* a_gm[2];
#pragma unroll
    for (int i = 0; i < 2; ++i) {
        int idx = tid + 256 * i, r = idx >> 2, c = idx & 3;
        a_sm[i] = r * 64 + ((c ^ ((r >> 1) & 3)) * 16);
        a_gm[i] = gA + (size_t)r * K_TOT + c * 8;
    }
    uint32_t b_sm[4]; const __half* b_gm[4];
#pragma unroll
    for (int i = 0; i < 4; ++i) {
        int idx = tid + 256 * i, r = idx >> 2, c = idx & 3;
        b_sm[i] = A_STAGE + r * 64 + ((c ^ ((r >> 1) & 3)) * 16);
        b_gm[i] = gB + (size_t)r * K_TOT + c * 8;
    }

    // --- ldmatrix lane address offsets (kk=0); kk=1 -> XOR 32 ---
    const int rA = warp_m + (lane & 15);
    const uint32_t aoff = rA * 64 + ((((lane >> 4) & 1) ^ ((rA >> 1) & 3)) * 16);
    const int rB = warp_n + (lane & 7) + ((lane >> 4) << 3);
    const uint32_t boff = A_STAGE + rB * 64 + ((((lane >> 3) & 1) ^ ((rB >> 1) & 3)) * 16);

    float acc[4][8][4];
#pragma unroll
    for (int i = 0; i < 4; ++i)
#pragma unroll
        for (int j = 0; j < 8; ++j)
#pragma unroll
            for (int e = 0; e < 4; ++e) acc[i][j][e] = 0.f;

    // prologue: prefetch 3 k-tiles
#pragma unroll
    for (int s = 0; s < STAGES - 1; ++s) {
        uint32_t base = sb + s * STAGE_BYTES;
#pragma unroll
        for (int i = 0; i < 2; ++i) cp_async16(base + a_sm[i], a_gm[i] + s * TILE_K);
#pragma unroll
        for (int i = 0; i < 4; ++i) cp_async16(base + b_sm[i], b_gm[i] + s * TILE_K);
        cp_commit();
    }

    for (int kt = 0; kt < NK; ++kt) {
        cp_wait<STAGES - 2>();
        __syncthreads();

        const uint32_t sbase = sb + (kt & (STAGES - 1)) * STAGE_BYTES;
#pragma unroll
        for (int kk = 0; kk < 2; ++kk) {
            const uint32_t kx = kk << 5;
            uint32_t a[4][4], b[4][4];
#pragma unroll
            for (int i = 0; i < 4; ++i) ldsm4(a[i], (sbase + aoff + i * 1024) ^ kx);
#pragma unroll
            for (int j = 0; j < 4; ++j) ldsm4(b[j], (sbase + boff + j * 1024) ^ kx);
#pragma unroll
            for (int i = 0; i < 4; ++i)
#pragma unroll
                for (int j = 0; j < 8; ++j) {
                    const uint32_t* bt = b[j >> 1];
                    mma16816(acc[i][j], a[i], bt[(j & 1) * 2], bt[(j & 1) * 2 + 1]);
                }
        }

        // prefetch k-tile kt+3 into stage (kt+3)%4 (fully consumed at kt-1;
        // the __syncthreads above makes that visible to all threads)
        if (kt + STAGES - 1 < NK) {
            const int kn = kt + STAGES - 1;
            uint32_t base = sb + (kn & (STAGES - 1)) * STAGE_BYTES;
#pragma unroll
            for (int i = 0; i < 2; ++i) cp_async16(base + a_sm[i], a_gm[i] + kn * TILE_K);
#pragma unroll
            for (int i = 0; i < 4; ++i) cp_async16(base + b_sm[i], b_gm[i] + kn * TILE_K);
        }
        cp_commit();
    }

    // --- epilogue: scale by s_w[n], write fp32 ---
#pragma unroll
    for (int i = 0; i < 4; ++i) {
        const int r0 = mt * TILE_M + warp_m + i * 16 + (lane >> 2);
        float* o0 = out + (size_t)r0 * N_TOT + nt * TILE_N;
        float* o1 = o0 + 8 * N_TOT;
#pragma unroll
        for (int j = 0; j < 8; ++j) {
            const int col = warp_n + j * 8 + (lane & 3) * 2;
            const float sw0 = s_sw[col], sw1 = s_sw[col + 1];
            float2 v0 = make_float2(acc[i][j][0] * sw0, acc[i][j][1] * sw1);
            float2 v1 = make_float2(acc[i][j][2] * sw0, acc[i][j][3] * sw1);
            *reinterpret_cast<float2*>(o0 + col) = v0;
            *reinterpret_cast<float2*>(o1 + col) = v1;
        }
    }
}

// ---------------------------------------------------------------------------
// launch
// ---------------------------------------------------------------------------
extern "C" void kernel_launch(void* const* d_in, const int* in_sizes, int n_in,
                              void* d_out, int out_size) {
    (void)in_sizes; (void)n_in; (void)out_size;
    const float* x = (const float*)d_in[0];   // [4,2048,4096] fp32
    const float* w = (const float*)d_in[1];   // [4096,4096]   fp32
    float* out = (float*)d_out;               // [4,2048,4096] fp32

    quant_x_kernel<<<M_TOT, 256>>>(x);
    quant_w_kernel<<<N_TOT, 256>>>(w);

    static bool attr_set = false;
    if (!attr_set) {
        cudaFuncSetAttribute(bitlinear_gemm,
                             cudaFuncAttributeMaxDynamicSharedMemorySize, SMEM_DYN);
        attr_set = true;
    }
    dim3 grid(N_TOT / TILE_N, M_TOT / TILE_M);   // (16, 64)
    bitlinear_gemm<<<grid, 256, SMEM_DYN>>>(out);
}